// round 14
// baseline (speedup 1.0000x reference)
#include <cuda_runtime.h>
#include <cstdint>

// GRU: B=64, T=2048, I=256, H=256.  out = concat(out[B,T,H], hN[B,H]) fp32.
//
// 16 clusters x 8 CTAs (128 SMs). Cluster owns 4 batches; CTA rank owns
// j in [32r,32r+32) => fused rows {j,256+j,512+j}. 512 threads; thread
// (jj,kc) holds 3 gate rows x 32-float fused-K chunk in regs (96 floats).
// Warp = 2 j x 16 kc  =>  after GEMM, a 3-round shfl butterfly within
// kc-octets (h-part kc<8, x-part kc>=8) + one xor-8 exchange yields the
// complete per-(j,b) gate sums IN-WARP: no accS SMEM, no __syncthreads.
// Per step: GEMM -> shfl reduce -> elementwise -> DSMEM h-broadcast ->
// cluster.arrive -> x(t+2) prefetch (x triple-buffered) -> cluster.wait.

static constexpr int B_  = 64;
static constexpr int T_  = 2048;
static constexpr int I_  = 256;
static constexpr int H_  = 256;

static constexpr int CL      = 8;
static constexpr int NB      = 4;
static constexpr int NCL     = 16;
static constexpr int THREADS = 512;    // 32 j x 16 kc
static constexpr int CHS     = 36;     // 32-float chunk + 4 pad
static constexpr int ABS     = 8 * CHS;     // 288 floats: one batch (8 chunks)
static constexpr int APH     = NB * ABS;    // 1152: one h parity
static constexpr int APX     = NB * ABS;    // 1152: one x slab

typedef unsigned long long u64;

__device__ __forceinline__ void fma2(u64 &acc, u64 a, u64 b) {
    asm("fma.rn.f32x2 %0, %1, %2, %0;" : "+l"(acc) : "l"(a), "l"(b));
}
__device__ __forceinline__ float sum2(u64 v) {
    float lo, hi;
    asm("mov.b64 {%0,%1}, %2;" : "=f"(lo), "=f"(hi) : "l"(v));
    return lo + hi;
}
__device__ __forceinline__ uint32_t smem_u32(const void* p) {
    return (uint32_t)__cvta_generic_to_shared(p);
}
__device__ __forceinline__ void cluster_arrive_() {
    asm volatile("barrier.cluster.arrive.aligned;" ::: "memory");
}
__device__ __forceinline__ void cluster_wait_() {
    asm volatile("barrier.cluster.wait.aligned;" ::: "memory");
}
__device__ __forceinline__ uint32_t ctarank_() {
    uint32_t r;
    asm("mov.u32 %0, %%cluster_ctarank;" : "=r"(r));
    return r;
}
__device__ __forceinline__ float sigmoidf_(float x) {
    return 1.0f / (1.0f + __expf(-x));
}
__device__ __forceinline__ float tanhf_fast_(float x) {
    return 1.0f - 2.0f / (1.0f + __expf(2.0f * x));
}

__global__ void __launch_bounds__(THREADS, 1) __cluster_dims__(CL, 1, 1)
gru_persistent_kernel(const float* __restrict__ x,
                      const float* __restrict__ h0,
                      const float* __restrict__ Wih,
                      const float* __restrict__ bih,
                      const float* __restrict__ Whh,
                      const float* __restrict__ bhh,
                      float* __restrict__ out,
                      int out_size)
{
    __shared__ float Aph[2 * APH];   // [parity][b][8 chunks][36]  (h state)
    __shared__ float Apx[3 * APX];   // [slab t%3][b][8 chunks][36] (x inputs)

    const int tid  = threadIdx.x;
    const int rank = (int)ctarank_();
    const int b0   = (blockIdx.x >> 3) * NB;

    const int kc = tid & 15;         // fused-K chunk (lane-varying; kc<8: h, >=8: x)
    const int jj = tid >> 4;         // j within slice, 0..31
    const int jg = (rank << 5) + jj; // global j

    // ---- weights in registers: rows {jg, 256+jg, 512+jg}, 32-float chunk
    ulonglong2 w[3][8];
    {
        const float* base = (kc < 8) ? Whh : Wih;
        const int colb = (kc & 7) << 5;
        #pragma unroll
        for (int g = 0; g < 3; ++g) {
            const float* src = base + (size_t)((g << 8) + jg) * 256 + colb;
            #pragma unroll
            for (int k4 = 0; k4 < 8; ++k4)
                w[g][k4] = *(const ulonglong2*)(src + (k4 << 2));
        }
    }

    // ---- per-thread biases (combined where possible)
    const float b_r  = bhh[jg]       + bih[jg];
    const float b_hc = bhh[256 + jg];
    const float b_ic = bih[256 + jg];
    const float b_u  = bhh[512 + jg] + bih[512 + jg];

    // ---- precomputed DSMEM base addresses of peers' Aph
    const uint32_t aph_u32 = smem_u32(Aph);
    uint32_t rbase[CL];
    #pragma unroll
    for (int pr = 0; pr < CL; ++pr)
        asm("mapa.shared::cluster.u32 %0, %1, %2;"
            : "=r"(rbase[pr]) : "r"(aph_u32), "r"(pr));

    // ---- h0 -> Aph[0], x(0) -> Apx[0]
    if (tid < NB * 64) {
        int b = tid >> 6, kk = tid & 63;
        int ch = kk >> 3, pos = (kk & 7) << 2;
        *(float4*)(Aph + b * ABS + ch * CHS + pos) =
            *(const float4*)(h0 + (size_t)(b0 + b) * H_ + (kk << 2));
        *(float4*)(Apx + b * ABS + ch * CHS + pos) =
            *(const float4*)(x + ((size_t)(b0 + b) * T_) * I_ + (kk << 2));
    }
    // ---- cp.async x(1) -> Apx[1]
    const uint32_t apx_u32 = smem_u32(Apx);
    if (tid < NB * 64) {
        int b = tid >> 6, kk = tid & 63;
        int ch = kk >> 3, pos = (kk & 7) << 2;
        const float* gsrc = x + ((size_t)(b0 + b) * T_ + 1) * I_ + (kk << 2);
        uint32_t s = apx_u32 + (uint32_t)((APX + b * ABS + ch * CHS + pos) * 4);
        asm volatile("cp.async.ca.shared.global [%0], [%1], 16;" :: "r"(s), "l"(gsrc));
    }
    asm volatile("cp.async.commit_group;");

    cluster_arrive_();
    cluster_wait_();

    const int myb    = kc & 3;                 // batch for the exchange/writer
    const bool writer = (kc < 4);              // 8 writer lanes per warp
    const int hoff_j = (jg >> 5) * CHS + (jg & 31);
    const size_t BTH = (size_t)B_ * T_ * H_;

    int s2 = 0;                                // x slab = t % 3

    for (int t = 0; t < T_; ++t) {
        const int p  = t & 1;
        const int pn = p ^ 1;

        // ---- 1. GEMM: 3 gates x 4 batches over this thread's 32-K chunk
        u64 c0[4] = {0,0,0,0}, c1[4] = {0,0,0,0}, c2[4] = {0,0,0,0};
        {
            const float* A = (kc < 8) ? (Aph + p * APH + kc * CHS)
                                      : (Apx + s2 * APX + (kc - 8) * CHS);
            #pragma unroll
            for (int k4 = 0; k4 < 8; ++k4) {
                ulonglong2 v0 = *(const ulonglong2*)(A + 0 * ABS + (k4 << 2));
                ulonglong2 v1 = *(const ulonglong2*)(A + 1 * ABS + (k4 << 2));
                ulonglong2 v2 = *(const ulonglong2*)(A + 2 * ABS + (k4 << 2));
                ulonglong2 v3 = *(const ulonglong2*)(A + 3 * ABS + (k4 << 2));
                ulonglong2 w0 = w[0][k4], w1 = w[1][k4], w2 = w[2][k4];
                fma2(c0[0], v0.x, w0.x); fma2(c0[0], v0.y, w0.y);
                fma2(c0[1], v1.x, w0.x); fma2(c0[1], v1.y, w0.y);
                fma2(c0[2], v2.x, w0.x); fma2(c0[2], v2.y, w0.y);
                fma2(c0[3], v3.x, w0.x); fma2(c0[3], v3.y, w0.y);
                fma2(c1[0], v0.x, w1.x); fma2(c1[0], v0.y, w1.y);
                fma2(c1[1], v1.x, w1.x); fma2(c1[1], v1.y, w1.y);
                fma2(c1[2], v2.x, w1.x); fma2(c1[2], v2.y, w1.y);
                fma2(c1[3], v3.x, w1.x); fma2(c1[3], v3.y, w1.y);
                fma2(c2[0], v0.x, w2.x); fma2(c2[0], v0.y, w2.y);
                fma2(c2[1], v1.x, w2.x); fma2(c2[1], v1.y, w2.y);
                fma2(c2[2], v2.x, w2.x); fma2(c2[2], v2.y, w2.y);
                fma2(c2[3], v3.x, w2.x); fma2(c2[3], v3.y, w2.y);
            }
        }

        // ---- 2. in-warp butterfly within kc-octets (h and x stay separate)
        float s0[4], s1[4], s2f[4];
        #pragma unroll
        for (int b = 0; b < 4; ++b) { s0[b] = sum2(c0[b]); s1[b] = sum2(c1[b]); s2f[b] = sum2(c2[b]); }
        #pragma unroll
        for (int m = 1; m <= 4; m <<= 1) {
            #pragma unroll
            for (int b = 0; b < 4; ++b) {
                s0[b]  += __shfl_xor_sync(0xffffffffu, s0[b],  m);
                s1[b]  += __shfl_xor_sync(0xffffffffu, s1[b],  m);
                s2f[b] += __shfl_xor_sync(0xffffffffu, s2f[b], m);
            }
        }
        // select own-batch values, exchange h<->x halves (xor 8)
        float vr = (myb & 2) ? ((myb & 1) ? s0[3]  : s0[2])  : ((myb & 1) ? s0[1]  : s0[0]);
        float vc = (myb & 2) ? ((myb & 1) ? s1[3]  : s1[2])  : ((myb & 1) ? s1[1]  : s1[0]);
        float vu = (myb & 2) ? ((myb & 1) ? s2f[3] : s2f[2]) : ((myb & 1) ? s2f[1] : s2f[0]);
        float or_ = __shfl_xor_sync(0xffffffffu, vr, 8);
        float oc  = __shfl_xor_sync(0xffffffffu, vc, 8);
        float ou  = __shfl_xor_sync(0xffffffffu, vu, 8);

        // ---- 3. elementwise GRU + out + DSMEM h-broadcast (writer lanes)
        if (writer) {
            float rg = sigmoidf_(vr + or_ + b_r);     // vr=h-part, or_=x-part
            float ug = sigmoidf_(vu + ou + b_u);
            float n  = tanhf_fast_((oc + b_ic) + rg * (vc + b_hc));

            const int hoff = myb * ABS + hoff_j;
            float hold = Aph[p * APH + hoff];
            float hy   = hold + ug * (n - hold);

            out[((size_t)(b0 + myb) * T_ + t) * H_ + jg] = hy;

            const uint32_t off = (uint32_t)((pn * APH + hoff) * 4);
            #pragma unroll
            for (int pr = 0; pr < CL; ++pr)
                asm volatile("st.shared::cluster.f32 [%0], %1;"
                             :: "r"(rbase[pr] + off), "f"(hy));
        }

        // ---- 4. release broadcasts; prefetch x(t+2) in the barrier shadow
        cluster_arrive_();

        const int spf = (s2 == 0) ? 2 : s2 - 1;      // (t+2) % 3
        if (t + 2 < T_ && tid < NB * 64) {
            int b = tid >> 6, kk = tid & 63;
            int ch = kk >> 3, pos = (kk & 7) << 2;
            const float* gsrc = x + ((size_t)(b0 + b) * T_ + (t + 2)) * I_ + (kk << 2);
            uint32_t s = apx_u32 + (uint32_t)((spf * APX + b * ABS + ch * CHS + pos) * 4);
            asm volatile("cp.async.ca.shared.global [%0], [%1], 16;" :: "r"(s), "l"(gsrc));
        }
        asm volatile("cp.async.commit_group;");
        asm volatile("cp.async.wait_group 1;" ::: "memory");  // x(t+1) landed

        cluster_wait_();                              // peers' h(t+1) visible

        s2 = (s2 == 2) ? 0 : s2 + 1;
    }

    // ---- final hidden state: h(T) in parity 0 (T even)
    if (out_size >= (int)(BTH + (size_t)B_ * H_)) {
        for (int i = tid; i < NB * H_; i += THREADS) {
            int b = i >> 8, j = i & 255;
            out[BTH + (size_t)(b0 + b) * H_ + j] =
                Aph[b * ABS + (j >> 5) * CHS + (j & 31)];
        }
    }
}

extern "C" void kernel_launch(void* const* d_in, const int* in_sizes, int n_in,
                              void* d_out, int out_size) {
    const float* x    = (const float*)d_in[0];
    const float* h0   = (const float*)d_in[1];
    const float* Wih  = (const float*)d_in[2];
    const float* bih  = (const float*)d_in[3];
    const float* Whh  = (const float*)d_in[4];
    const float* bhh  = (const float*)d_in[5];
    float* out = (float*)d_out;

    gru_persistent_kernel<<<NCL * CL, THREADS>>>(
        x, h0, Wih, bih, Whh, bhh, out, out_size);
}

// round 15
// speedup vs baseline: 1.1164x; 1.1164x over previous
#include <cuda_runtime.h>
#include <cstdint>

// GRU: B=64, T=2048, I=256, H=256.  out = concat(out[B,T,H], hN[B,H]) fp32.
//
// 16 clusters x 8 CTAs (128 SMs). Cluster owns 4 batches; CTA rank owns
// j in [32r,32r+32) => fused rows {j,256+j,512+j} (96 rows x 512 fused K).
// 512 threads = 16 warps: warp w = fused-K chunk kc=w (kc<8: W_hh/h-part,
// kc>=8: W_ih/x-part); lane = jj. Thread holds 3 gate rows x 32-float chunk
// in registers (96 floats). GEMM A-loads are warp-uniform -> broadcast LDS,
// 1 wavefront each, zero bank conflicts. Partials -> accS (conflict-free),
// reduced by 384 threads (one per (b,j,gate)) into gsum, then 128 writers
// do the GRU nonlinearity + DSMEM h-broadcast. One cluster barrier/step.

static constexpr int B_  = 64;
static constexpr int T_  = 2048;
static constexpr int I_  = 256;
static constexpr int H_  = 256;

static constexpr int CL      = 8;
static constexpr int NB      = 4;
static constexpr int NCL     = 16;
static constexpr int THREADS = 512;          // 16 warps: warp=kc, lane=jj
static constexpr int CHS     = 36;           // 32-float A chunk + pad
static constexpr int APB     = 16 * CHS;     // 576 floats per batch (ch<8 h, ch>=8 x)
static constexpr int APP     = NB * APB;     // 2304 per parity
static constexpr int ARS     = 5;            // accS row stride
static constexpr int ASLAB   = 96 * ARS + 2; // 482 (mod 32 = 2)

typedef unsigned long long u64;

__device__ __forceinline__ void fma2(u64 &acc, u64 a, u64 b) {
    asm("fma.rn.f32x2 %0, %1, %2, %0;" : "+l"(acc) : "l"(a), "l"(b));
}
__device__ __forceinline__ float sum2(u64 v) {
    float lo, hi;
    asm("mov.b64 {%0,%1}, %2;" : "=f"(lo), "=f"(hi) : "l"(v));
    return lo + hi;
}
__device__ __forceinline__ uint32_t smem_u32(const void* p) {
    return (uint32_t)__cvta_generic_to_shared(p);
}
__device__ __forceinline__ void cluster_arrive_() {
    asm volatile("barrier.cluster.arrive.aligned;" ::: "memory");
}
__device__ __forceinline__ void cluster_wait_() {
    asm volatile("barrier.cluster.wait.aligned;" ::: "memory");
}
__device__ __forceinline__ uint32_t ctarank_() {
    uint32_t r;
    asm("mov.u32 %0, %%cluster_ctarank;" : "=r"(r));
    return r;
}
__device__ __forceinline__ float sigmoidf_(float x) {
    return 1.0f / (1.0f + __expf(-x));
}
__device__ __forceinline__ float tanhf_fast_(float x) {
    return 1.0f - 2.0f / (1.0f + __expf(2.0f * x));
}

__global__ void __launch_bounds__(THREADS, 1) __cluster_dims__(CL, 1, 1)
gru_persistent_kernel(const float* __restrict__ x,
                      const float* __restrict__ h0,
                      const float* __restrict__ Wih,
                      const float* __restrict__ bih,
                      const float* __restrict__ Whh,
                      const float* __restrict__ bhh,
                      float* __restrict__ out,
                      int out_size)
{
    __shared__ float Ap[2 * APP];        // [parity][b][16 ch][36]
    __shared__ float accS[16 * ASLAB];   // [kc slab 482][row*5 + b]
    __shared__ float gsum[4 * 128];      // [slot r,hc,ic,u][b*32+j]
    __shared__ float bias[4 * 32];       // r-comb, hc, ic, u-comb

    const int tid  = threadIdx.x;
    const int rank = (int)ctarank_();
    const int b0   = (blockIdx.x >> 3) * NB;

    const int kc = tid >> 5;             // warp index = fused-K chunk
    const int jj = tid & 31;             // lane = j within slice
    const int jg = (rank << 5) + jj;     // global j

    // ---- weights in registers: rows {jg, 256+jg, 512+jg}, 32-float chunk kc
    ulonglong2 w0[8], w1[8], w2[8];
    {
        const float* base = (kc < 8) ? Whh : Wih;
        const int colb = (kc & 7) << 5;
        const float* s0 = base + (size_t)(jg)       * 256 + colb;
        const float* s1 = base + (size_t)(256 + jg) * 256 + colb;
        const float* s2 = base + (size_t)(512 + jg) * 256 + colb;
        #pragma unroll
        for (int k4 = 0; k4 < 8; ++k4) {
            w0[k4] = *(const ulonglong2*)(s0 + (k4 << 2));
            w1[k4] = *(const ulonglong2*)(s1 + (k4 << 2));
            w2[k4] = *(const ulonglong2*)(s2 + (k4 << 2));
        }
    }

    // ---- combined biases
    if (tid < 32) {
        int j = (rank << 5) + tid;
        bias[tid]      = bhh[j]       + bih[j];
        bias[32 + tid] = bhh[256 + j];
        bias[64 + tid] = bih[256 + j];
        bias[96 + tid] = bhh[512 + j] + bih[512 + j];
    }

    // ---- h0 + x(0) into Ap[0]
    if (tid < NB * 64) {
        int b = tid >> 6, kk = tid & 63;
        int ch = kk >> 3, pos = (kk & 7) << 2;
        *(float4*)(Ap + b * APB + ch * CHS + pos) =
            *(const float4*)(h0 + (size_t)(b0 + b) * H_ + (kk << 2));
        *(float4*)(Ap + b * APB + (8 + ch) * CHS + pos) =
            *(const float4*)(x + ((size_t)(b0 + b) * T_) * I_ + (kk << 2));
    }

    // ---- cp.async x(1) -> Ap[1].x
    const uint32_t ap_u32 = smem_u32(Ap);
    if (tid < NB * 64) {
        int b = tid >> 6, kk = tid & 63;
        int ch = 8 + (kk >> 3), pos = (kk & 7) << 2;
        const float* gsrc = x + ((size_t)(b0 + b) * T_ + 1) * I_ + (kk << 2);
        uint32_t s = ap_u32 + (uint32_t)((APP + b * APB + ch * CHS + pos) * 4);
        asm volatile("cp.async.ca.shared.global [%0], [%1], 16;" :: "r"(s), "l"(gsrc));
    }
    asm volatile("cp.async.commit_group;");

    // ---- hoisted DSMEM peer bases
    uint32_t rbase[CL];
    #pragma unroll
    for (int pr = 0; pr < CL; ++pr)
        asm("mapa.shared::cluster.u32 %0, %1, %2;"
            : "=r"(rbase[pr]) : "r"(ap_u32), "r"(pr));

    cluster_arrive_();
    cluster_wait_();

    // elementwise roles
    const int eg   = tid >> 7;            // gate phase 0..2 (tid<384)
    const int ep   = tid & 127;           // pair = b*32 + j
    const int epb  = ep >> 5, epj = ep & 31;
    const int wb   = tid >> 5;            // writer batch (tid<128)
    const int wj   = tid & 31;
    const int wjg  = (rank << 5) + wj;
    const int whoff = wb * APB + (wjg >> 5) * CHS + (wjg & 31);
    const size_t BTH = (size_t)B_ * T_ * H_;

    for (int t = 0; t < T_; ++t) {
        const int p  = t & 1;
        const int pn = p ^ 1;

        // ---- 1. GEMM: 3 gates x 4 batches, broadcast A loads, two halves
        {
            const float* A = Ap + p * APP + kc * CHS;
            float* dst = accS + kc * ASLAB + jj * ARS;
            #pragma unroll
            for (int h = 0; h < 2; ++h) {
                const float* Aa = A + (2 * h) * APB;
                const float* Ab = Aa + APB;
                u64 c0a = 0, c1a = 0, c2a = 0, c0b = 0, c1b = 0, c2b = 0;
                #pragma unroll
                for (int k4 = 0; k4 < 8; ++k4) {
                    ulonglong2 va = *(const ulonglong2*)(Aa + (k4 << 2));
                    ulonglong2 vb = *(const ulonglong2*)(Ab + (k4 << 2));
                    ulonglong2 u0 = w0[k4], u1 = w1[k4], u2 = w2[k4];
                    fma2(c0a, va.x, u0.x); fma2(c0a, va.y, u0.y);
                    fma2(c1a, va.x, u1.x); fma2(c1a, va.y, u1.y);
                    fma2(c2a, va.x, u2.x); fma2(c2a, va.y, u2.y);
                    fma2(c0b, vb.x, u0.x); fma2(c0b, vb.y, u0.y);
                    fma2(c1b, vb.x, u1.x); fma2(c1b, vb.y, u1.y);
                    fma2(c2b, vb.x, u2.x); fma2(c2b, vb.y, u2.y);
                }
                dst[2 * h]                = sum2(c0a);
                dst[2 * h + 1]            = sum2(c0b);
                dst[32 * ARS + 2 * h]     = sum2(c1a);
                dst[32 * ARS + 2 * h + 1] = sum2(c1b);
                dst[64 * ARS + 2 * h]     = sum2(c2a);
                dst[64 * ARS + 2 * h + 1] = sum2(c2b);
            }
        }
        __syncthreads();

        // ---- 2a. gate-parallel reduction into gsum (threads 0..383)
        if (tid < 384) {
            const int rowb = (eg << 5) + epj;        // gate row base + j
            const float* s = accS + rowb * ARS + epb;
            if (eg == 1) {                           // candidate: h / x split
                float hc = 0.f, ic = 0.f;
                #pragma unroll
                for (int q = 0; q < 8; ++q)  hc += s[q * ASLAB];
                #pragma unroll
                for (int q = 8; q < 16; ++q) ic += s[q * ASLAB];
                gsum[128 + ep] = hc;
                gsum[256 + ep] = ic;
            } else {
                float v = 0.f;
                #pragma unroll
                for (int q = 0; q < 16; ++q) v += s[q * ASLAB];
                gsum[(eg == 0 ? 0 : 384) + ep] = v;
            }
        }
        // ---- 2b. prefetch x(t+2) into Ap[p].x (threads 256..511)
        if (t + 2 < T_ && tid >= 256) {
            int i4 = tid - 256;
            int b = i4 >> 6, kk = i4 & 63;
            int ch = 8 + (kk >> 3), pos = (kk & 7) << 2;
            const float* gsrc = x + ((size_t)(b0 + b) * T_ + (t + 2)) * I_ + (kk << 2);
            uint32_t s = ap_u32 + (uint32_t)((p * APP + b * APB + ch * CHS + pos) * 4);
            asm volatile("cp.async.ca.shared.global [%0], [%1], 16;" :: "r"(s), "l"(gsrc));
        }
        asm volatile("cp.async.commit_group;");
        __syncthreads();

        // ---- 3. writers: GRU nonlinearity + DSMEM h-broadcast (threads 0..127)
        if (tid < 128) {
            float rg = sigmoidf_(gsum[tid]       + bias[wj]);
            float ug = sigmoidf_(gsum[384 + tid] + bias[96 + wj]);
            float n  = tanhf_fast_((gsum[256 + tid] + bias[64 + wj])
                                   + rg * (gsum[128 + tid] + bias[32 + wj]));

            float hold = Ap[p * APP + whoff];
            float hy   = hold + ug * (n - hold);

            const uint32_t off = (uint32_t)((pn * APP + whoff) * 4);
            #pragma unroll
            for (int pr = 0; pr < CL; ++pr)
                asm volatile("st.shared::cluster.f32 [%0], %1;"
                             :: "r"(rbase[pr] + off), "f"(hy));

            out[((size_t)(b0 + wb) * T_ + t) * H_ + wjg] = hy;
        }
        asm volatile("cp.async.wait_group 1;" ::: "memory");  // x(t+1) landed

        // ---- 4. cluster barrier: release broadcasts / acquire peers'
        cluster_arrive_();
        cluster_wait_();
    }

    // ---- final hidden state: h(T) in parity 0 (T even)
    if (out_size >= (int)(BTH + (size_t)B_ * H_)) {
        for (int i = tid; i < NB * H_; i += THREADS) {
            int b = i >> 8, j = i & 255;
            out[BTH + (size_t)(b0 + b) * H_ + j] =
                Ap[b * APB + (j >> 5) * CHS + (j & 31)];
        }
    }
}

extern "C" void kernel_launch(void* const* d_in, const int* in_sizes, int n_in,
                              void* d_out, int out_size) {
    const float* x    = (const float*)d_in[0];
    const float* h0   = (const float*)d_in[1];
    const float* Wih  = (const float*)d_in[2];
    const float* bih  = (const float*)d_in[3];
    const float* Whh  = (const float*)d_in[4];
    const float* bhh  = (const float*)d_in[5];
    float* out = (float*)d_out;

    gru_persistent_kernel<<<NCL * CL, THREADS>>>(
        x, h0, Wih, bih, Whh, bhh, out, out_size);
}